// round 7
// baseline (speedup 1.0000x reference)
#include <cuda_runtime.h>
#include <math_constants.h>
#include <cstdint>

#define NH 16
#define HD 128
#define B_ 2
#define T_ 1024
#define XL_ 1024
#define KV_ 2048
#define BT_ 2048
#define DM 2048

// Scratch (device globals; no allocation allowed)
__device__ float g_qkv[BT_ * 3 * DM];            // 50 MB
__device__ float g_q[B_ * NH * T_ * HD];         // 16 MB
__device__ float g_k[B_ * NH * KV_ * HD];        // 32 MB
__device__ float g_v[B_ * NH * KV_ * HD];        // 32 MB
__device__ float g_y[BT_ * DM];                  // 16 MB

__device__ __forceinline__ uint32_t f2tf32(float f) {
    uint32_t u;
    asm("cvt.rna.tf32.f32 %0, %1;" : "=r"(u) : "f"(f));
    return u;
}

// ---------------------------------------------------------------------------
// C[M,N] = A[M,K] @ B[N,K]^T  via tf32 mma.sync.m16n8k8, fp32 accumulate.
// Block tile 128x128, K-step 16, 256 threads = 8 warps (2x4), warp tile 64x32.
// Double-buffered smem + register prefetch: one __syncthreads per K-step.
// ---------------------------------------------------------------------------
#define GS 2560                       // one 128x16 buffer (stride 20) in u32
#define GEMM_SMEM (4 * GS * 4)        // 2 bufs x (A+B) x 2560 u32 = 80 KB

__global__ __launch_bounds__(256) void tgemm_nt(const float* __restrict__ A,
                                                const float* __restrict__ B,
                                                float* __restrict__ C,
                                                int N, int K) {
    extern __shared__ uint32_t dynsm[];
    uint32_t* As = dynsm;             // [2][128*20]
    uint32_t* Bs = dynsm + 2 * GS;    // [2][128*20]
    const int tid = threadIdx.x;
    const int bm = blockIdx.y * 128;
    const int bn = blockIdx.x * 128;
    const int wid = tid >> 5, lane = tid & 31;
    const int g = lane >> 2, t = lane & 3;
    const int wm = (wid & 1) * 64;    // warp M offset in tile
    const int wn = (wid >> 1) * 32;   // warp N offset in tile

    // loader map: this thread fills rows r0 and r0+64, col-quad c4 (A and B)
    const int r0 = tid >> 2;
    const int c4 = (tid & 3) << 2;
    const float* ApL = A + (size_t)(bm + r0) * K + c4;
    const float* ApH = A + (size_t)(bm + r0 + 64) * K + c4;
    const float* BpL = B + (size_t)(bn + r0) * K + c4;
    const float* BpH = B + (size_t)(bn + r0 + 64) * K + c4;

    float acc[4][4][4];
#pragma unroll
    for (int mi = 0; mi < 4; mi++)
#pragma unroll
        for (int nj = 0; nj < 4; nj++)
#pragma unroll
            for (int r = 0; r < 4; r++) acc[mi][nj][r] = 0.f;

    float4 pa0, pa1, pb0, pb1;
    // preload k0 = 0
    pa0 = *(const float4*)(ApL);  pa1 = *(const float4*)(ApH);
    pb0 = *(const float4*)(BpL);  pb1 = *(const float4*)(BpH);
    {
        uint32_t ua0[4] = {f2tf32(pa0.x), f2tf32(pa0.y), f2tf32(pa0.z), f2tf32(pa0.w)};
        uint32_t ua1[4] = {f2tf32(pa1.x), f2tf32(pa1.y), f2tf32(pa1.z), f2tf32(pa1.w)};
        uint32_t ub0[4] = {f2tf32(pb0.x), f2tf32(pb0.y), f2tf32(pb0.z), f2tf32(pb0.w)};
        uint32_t ub1[4] = {f2tf32(pb1.x), f2tf32(pb1.y), f2tf32(pb1.z), f2tf32(pb1.w)};
        *(uint4*)&As[r0 * 20 + c4] = *(uint4*)ua0;
        *(uint4*)&As[(r0 + 64) * 20 + c4] = *(uint4*)ua1;
        *(uint4*)&Bs[r0 * 20 + c4] = *(uint4*)ub0;
        *(uint4*)&Bs[(r0 + 64) * 20 + c4] = *(uint4*)ub1;
    }
    __syncthreads();

    int buf = 0;
    for (int k0 = 0; k0 < K; k0 += 16) {
        const int nk = k0 + 16;
        const bool more = (nk < K);
        if (more) {   // prefetch next slice into registers (overlaps mma below)
            pa0 = *(const float4*)(ApL + nk);  pa1 = *(const float4*)(ApH + nk);
            pb0 = *(const float4*)(BpL + nk);  pb1 = *(const float4*)(BpH + nk);
        }

        const uint32_t* Ab = As + buf * GS;
        const uint32_t* Bb = Bs + buf * GS;
#pragma unroll
        for (int kk = 0; kk < 16; kk += 8) {
            uint32_t af[4][4], bf[4][2];
#pragma unroll
            for (int mi = 0; mi < 4; mi++) {
                int m0 = wm + mi * 16;
                af[mi][0] = Ab[(m0 + g) * 20 + kk + t];
                af[mi][1] = Ab[(m0 + g + 8) * 20 + kk + t];
                af[mi][2] = Ab[(m0 + g) * 20 + kk + t + 4];
                af[mi][3] = Ab[(m0 + g + 8) * 20 + kk + t + 4];
            }
#pragma unroll
            for (int nj = 0; nj < 4; nj++) {
                int n0 = wn + nj * 8;
                bf[nj][0] = Bb[(n0 + g) * 20 + kk + t];
                bf[nj][1] = Bb[(n0 + g) * 20 + kk + t + 4];
            }
#pragma unroll
            for (int mi = 0; mi < 4; mi++)
#pragma unroll
                for (int nj = 0; nj < 4; nj++) {
                    asm volatile(
                        "mma.sync.aligned.m16n8k8.row.col.f32.tf32.tf32.f32 "
                        "{%0,%1,%2,%3}, {%4,%5,%6,%7}, {%8,%9}, {%0,%1,%2,%3};"
                        : "+f"(acc[mi][nj][0]), "+f"(acc[mi][nj][1]),
                          "+f"(acc[mi][nj][2]), "+f"(acc[mi][nj][3])
                        : "r"(af[mi][0]), "r"(af[mi][1]), "r"(af[mi][2]), "r"(af[mi][3]),
                          "r"(bf[nj][0]), "r"(bf[nj][1]));
                }
        }

        if (more) {   // store next slice into the other buffer, single sync
            uint32_t* An = As + (buf ^ 1) * GS;
            uint32_t* Bn = Bs + (buf ^ 1) * GS;
            uint32_t ua0[4] = {f2tf32(pa0.x), f2tf32(pa0.y), f2tf32(pa0.z), f2tf32(pa0.w)};
            uint32_t ua1[4] = {f2tf32(pa1.x), f2tf32(pa1.y), f2tf32(pa1.z), f2tf32(pa1.w)};
            uint32_t ub0[4] = {f2tf32(pb0.x), f2tf32(pb0.y), f2tf32(pb0.z), f2tf32(pb0.w)};
            uint32_t ub1[4] = {f2tf32(pb1.x), f2tf32(pb1.y), f2tf32(pb1.z), f2tf32(pb1.w)};
            *(uint4*)&An[r0 * 20 + c4] = *(uint4*)ua0;
            *(uint4*)&An[(r0 + 64) * 20 + c4] = *(uint4*)ua1;
            *(uint4*)&Bn[r0 * 20 + c4] = *(uint4*)ub0;
            *(uint4*)&Bn[(r0 + 64) * 20 + c4] = *(uint4*)ub1;
            __syncthreads();
            buf ^= 1;
        }
    }

    // epilogue: c0,c1 -> row g, cols 2t,2t+1 ; c2,c3 -> row g+8
#pragma unroll
    for (int mi = 0; mi < 4; mi++) {
        int m0 = bm + wm + mi * 16;
#pragma unroll
        for (int nj = 0; nj < 4; nj++) {
            int n0 = bn + wn + nj * 8 + 2 * t;
            *(float2*)(C + (size_t)(m0 + g) * N + n0) =
                make_float2(acc[mi][nj][0], acc[mi][nj][1]);
            *(float2*)(C + (size_t)(m0 + g + 8) * N + n0) =
                make_float2(acc[mi][nj][2], acc[mi][nj][3]);
        }
    }
}

// ---------------------------------------------------------------------------
// RoPE on q and current-k + scatter into head-major buffers; copy v.
// ---------------------------------------------------------------------------
__global__ __launch_bounds__(256) void rope_scatter(const float* __restrict__ cosb,
                                                    const float* __restrict__ sinb) {
    int idx = blockIdx.x * blockDim.x + threadIdx.x;
    if (idx >= B_ * T_ * NH * 64) return;
    int i = idx & 63;
    int h = (idx >> 6) & 15;
    int t = (idx >> 10) & 1023;
    int b = idx >> 20;
    const float* base = g_qkv + (size_t)(b * T_ + t) * (3 * DM);
    float c = cosb[t * 64 + i], s = sinb[t * 64 + i];

    float q1 = base[h * HD + 2 * i], q2 = base[h * HD + 2 * i + 1];
    size_t qo = ((size_t)(b * NH + h) * T_ + t) * HD + 2 * i;
    g_q[qo]     = q1 * c - q2 * s;
    g_q[qo + 1] = q1 * s + q2 * c;

    float k1 = base[DM + h * HD + 2 * i], k2 = base[DM + h * HD + 2 * i + 1];
    size_t ko = ((size_t)(b * NH + h) * KV_ + XL_ + t) * HD + 2 * i;
    g_k[ko]     = k1 * c - k2 * s;
    g_k[ko + 1] = k1 * s + k2 * c;

    g_v[ko]     = base[2 * DM + h * HD + 2 * i];
    g_v[ko + 1] = base[2 * DM + h * HD + 2 * i + 1];
}

// ---------------------------------------------------------------------------
// XL memory: k_xl + pos_emb -> g_k[:,:,0:1024,:] ; v_xl -> g_v[:,:,0:1024,:]
// ---------------------------------------------------------------------------
__global__ __launch_bounds__(256) void xl_prep(const float* __restrict__ k_xl,
                                               const float* __restrict__ v_xl,
                                               const float* __restrict__ pos_emb) {
    int idx = blockIdx.x * blockDim.x + threadIdx.x;
    if (idx >= B_ * XL_ * (DM / 4)) return;
    int c4 = (idx & 511) << 2;
    int n = (idx >> 9) & 1023;
    int b = idx >> 19;
    int h = c4 >> 7;
    int d = c4 & 127;
    float4 kv = *(const float4*)(k_xl + (size_t)(b * XL_ + n) * DM + c4);
    float4 pe = *(const float4*)(pos_emb + (size_t)n * DM + c4);
    float4 vv = *(const float4*)(v_xl + (size_t)(b * XL_ + n) * DM + c4);
    size_t off = ((size_t)(b * NH + h) * KV_ + n) * HD + d;
    *(float4*)(g_k + off) = make_float4(kv.x + pe.x, kv.y + pe.y, kv.z + pe.z, kv.w + pe.w);
    *(float4*)(g_v + off) = vv;
}

// ---------------------------------------------------------------------------
// Flash attention: grid (T/64, B*NH), 256 threads.
// Phase 1: S = Q Kc^T via tf32 mma.m16n8k8 (8 warps, each 16x32 of the 64x64 S).
// Phase 2: online softmax + P @ Vc in fp32 (thread = (q-row, dim-quarter)).
// ---------------------------------------------------------------------------
#define ATTN_SMEM ((3 * 64 * 132 + 64 * 65) * 4)

__global__ __launch_bounds__(256) void attn_kernel(const int* __restrict__ causal_p) {
    extern __shared__ float sm[];
    uint32_t* Qu = (uint32_t*)sm;              // 64 x 132 (tf32 bits)
    uint32_t* Ku = (uint32_t*)(sm + 64 * 132); // 64 x 132 (tf32 bits)
    float* Vs = sm + 2 * 64 * 132;             // 64 x 132 (fp32)
    float* Ss = sm + 3 * 64 * 132;             // 64 x 65
    const int bh = blockIdx.y;
    const int qt = blockIdx.x;
    const int tid = threadIdx.x;
    const bool causal = (*causal_p) != 0;
    const float scale = 0.08838834764831845f;   // 1/sqrt(128)

    // load Q tile, convert to tf32 once
    const float* Qg = g_q + ((size_t)bh * T_ + qt * 64) * HD;
    for (int i = tid; i < 64 * 32; i += 256) {
        int r = i >> 5, c4 = (i & 31) << 2;
        float4 q4 = *(const float4*)(Qg + r * HD + c4);
        uint32_t uq[4] = {f2tf32(q4.x), f2tf32(q4.y), f2tf32(q4.z), f2tf32(q4.w)};
        *(uint4*)&Qu[r * 132 + c4] = *(uint4*)uq;
    }

    const int wid = tid >> 5, lane = tid & 31;
    const int g = lane >> 2, t = lane & 3;
    const int wm = (wid >> 1) << 4;   // warp M offset: 4 warps x 16 rows
    const int wn = (wid & 1) << 5;    // warp N offset: 2 warps x 32 cols

    const int qr = tid & 63;
    const int dq = tid >> 6;
    const int qg = qt * 64 + qr;

    float m = -CUDART_INF_F, l = 0.f;
    float o[32];
#pragma unroll
    for (int d = 0; d < 32; d++) o[d] = 0.f;

    for (int k0 = 0; k0 < KV_; k0 += 64) {
        __syncthreads();   // prev phase-2 done before overwriting K/V
        const float* Kg = g_k + ((size_t)bh * KV_ + k0) * HD;
        const float* Vg = g_v + ((size_t)bh * KV_ + k0) * HD;
        for (int i = tid; i < 64 * 32; i += 256) {
            int r = i >> 5, c4 = (i & 31) << 2;
            float4 k4 = *(const float4*)(Kg + r * HD + c4);
            uint32_t uk[4] = {f2tf32(k4.x), f2tf32(k4.y), f2tf32(k4.z), f2tf32(k4.w)};
            *(uint4*)&Ku[r * 132 + c4] = *(uint4*)uk;
            *(float4*)(Vs + r * 132 + c4) = *(const float4*)(Vg + r * HD + c4);
        }
        __syncthreads();

        // ---- phase 1: S tile via tensor cores ----
        float sacc[4][4];
#pragma unroll
        for (int nj = 0; nj < 4; nj++)
#pragma unroll
            for (int r = 0; r < 4; r++) sacc[nj][r] = 0.f;

#pragma unroll 4
        for (int kk = 0; kk < HD; kk += 8) {
            uint32_t af[4];
            af[0] = Qu[(wm + g) * 132 + kk + t];
            af[1] = Qu[(wm + g + 8) * 132 + kk + t];
            af[2] = Qu[(wm + g) * 132 + kk + t + 4];
            af[3] = Qu[(wm + g + 8) * 132 + kk + t + 4];
#pragma unroll
            for (int nj = 0; nj < 4; nj++) {
                int n0 = wn + nj * 8;
                uint32_t bf0 = Ku[(n0 + g) * 132 + kk + t];
                uint32_t bf1 = Ku[(n0 + g) * 132 + kk + t + 4];
                asm volatile(
                    "mma.sync.aligned.m16n8k8.row.col.f32.tf32.tf32.f32 "
                    "{%0,%1,%2,%3}, {%4,%5,%6,%7}, {%8,%9}, {%0,%1,%2,%3};"
                    : "+f"(sacc[nj][0]), "+f"(sacc[nj][1]),
                      "+f"(sacc[nj][2]), "+f"(sacc[nj][3])
                    : "r"(af[0]), "r"(af[1]), "r"(af[2]), "r"(af[3]),
                      "r"(bf0), "r"(bf1));
            }
        }
#pragma unroll
        for (int nj = 0; nj < 4; nj++) {
            int col = wn + nj * 8 + 2 * t;
            int colg = k0 + col;
            int row0g = qt * 64 + wm + g;
#pragma unroll
            for (int half = 0; half < 2; half++) {
                int row = wm + g + half * 8;
                int rowg = row0g + half * 8;
                float s0 = sacc[nj][half * 2 + 0] * scale;
                float s1 = sacc[nj][half * 2 + 1] * scale;
                if (causal) {
                    if (colg > rowg + (KV_ - T_)) s0 = -CUDART_INF_F;
                    if (colg + 1 > rowg + (KV_ - T_)) s1 = -CUDART_INF_F;
                }
                Ss[row * 65 + col] = s0;
                Ss[row * 65 + col + 1] = s1;
            }
        }
        __syncthreads();

        // ---- phase 2: online softmax + PV (fp32) ----
        float cmax = -CUDART_INF_F;
#pragma unroll 8
        for (int j = 0; j < 64; j++) cmax = fmaxf(cmax, Ss[qr * 65 + j]);
        float mnew = fmaxf(m, cmax);
        float corr = (m == -CUDART_INF_F) ? 0.f : __expf(m - mnew);
        l *= corr;
#pragma unroll
        for (int d = 0; d < 32; d++) o[d] *= corr;

        const float* vbase = Vs + (dq << 5);
#pragma unroll 2
        for (int j = 0; j < 64; j++) {
            float p = __expf(Ss[qr * 65 + j] - mnew);
            l += p;
            const float4* vr = (const float4*)(vbase + j * 132);
#pragma unroll
            for (int d4 = 0; d4 < 8; d4++) {
                float4 vv = vr[d4];
                o[d4 * 4 + 0] = fmaf(p, vv.x, o[d4 * 4 + 0]);
                o[d4 * 4 + 1] = fmaf(p, vv.y, o[d4 * 4 + 1]);
                o[d4 * 4 + 2] = fmaf(p, vv.z, o[d4 * 4 + 2]);
                o[d4 * 4 + 3] = fmaf(p, vv.w, o[d4 * 4 + 3]);
            }
        }
        m = mnew;
    }

    // epilogue: write y in (b, t, h*HD) layout for the proj GEMM
    int b = bh >> 4, h = bh & 15;
    float inv = 1.0f / l;
    float* yp = g_y + (size_t)(b * T_ + qg) * DM + h * HD + (dq << 5);
#pragma unroll
    for (int d4 = 0; d4 < 8; d4++)
        *(float4*)(yp + d4 * 4) = make_float4(o[d4 * 4] * inv, o[d4 * 4 + 1] * inv,
                                              o[d4 * 4 + 2] * inv, o[d4 * 4 + 3] * inv);
}

// ---------------------------------------------------------------------------
extern "C" void kernel_launch(void* const* d_in, const int* in_sizes, int n_in,
                              void* d_out, int out_size) {
    const float* x       = (const float*)d_in[0];
    const float* cosb    = (const float*)d_in[1];
    const float* sinb    = (const float*)d_in[2];
    const float* k_xl    = (const float*)d_in[3];
    const float* v_xl    = (const float*)d_in[4];
    const float* pos_emb = (const float*)d_in[5];
    const float* w_qkv   = (const float*)d_in[6];
    const float* w_proj  = (const float*)d_in[7];
    const int*   is_causal = (const int*)d_in[8];
    float* out = (float*)d_out;

    float *qkv_p, *y_p;
    cudaGetSymbolAddress((void**)&qkv_p, g_qkv);
    cudaGetSymbolAddress((void**)&y_p, g_y);

    cudaFuncSetAttribute(tgemm_nt, cudaFuncAttributeMaxDynamicSharedMemorySize, GEMM_SMEM);
    cudaFuncSetAttribute(attn_kernel, cudaFuncAttributeMaxDynamicSharedMemorySize, ATTN_SMEM);

    // 1) qkv = x @ w_qkv^T   (2048 x 6144 x 2048), tf32 tensor cores, pipelined
    tgemm_nt<<<dim3(3 * DM / 128, BT_ / 128), 256, GEMM_SMEM>>>(x, w_qkv, qkv_p, 3 * DM, DM);

    // 2) RoPE + scatter, XL prep
    rope_scatter<<<(B_ * T_ * NH * 64) / 256, 256>>>(cosb, sinb);
    xl_prep<<<(B_ * XL_ * (DM / 4)) / 256, 256>>>(k_xl, v_xl, pos_emb);

    // 3) attention (tf32 scores, fp32 softmax/PV)
    attn_kernel<<<dim3(T_ / 64, B_ * NH), 256, ATTN_SMEM>>>(is_causal);

    // 4) out = y @ w_proj^T  (2048 x 2048 x 2048), tf32 tensor cores, pipelined
    tgemm_nt<<<dim3(DM / 128, BT_ / 128), 256, GEMM_SMEM>>>(y_p, w_proj, out, DM, DM);
}

// round 8
// speedup vs baseline: 1.4031x; 1.4031x over previous
#include <cuda_runtime.h>
#include <math_constants.h>
#include <cstdint>

#define NH 16
#define HD 128
#define B_ 2
#define T_ 1024
#define XL_ 1024
#define KV_ 2048
#define BT_ 2048
#define DM 2048

// Scratch (device globals; no allocation allowed)
__device__ float g_qkv[BT_ * 3 * DM];            // 50 MB
__device__ float g_q[B_ * NH * T_ * HD];         // 16 MB
__device__ float g_k[B_ * NH * KV_ * HD];        // 32 MB
__device__ float g_v[B_ * NH * KV_ * HD];        // 32 MB
__device__ float g_y[BT_ * DM];                  // 16 MB

__device__ __forceinline__ uint32_t f2tf32(float f) {
    uint32_t u;
    asm("cvt.rna.tf32.f32 %0, %1;" : "=r"(u) : "f"(f));
    return u;
}

#define MMA_TF32(d0,d1,d2,d3,a0,a1,a2,a3,b0,b1)                                \
    asm volatile(                                                              \
        "mma.sync.aligned.m16n8k8.row.col.f32.tf32.tf32.f32 "                  \
        "{%0,%1,%2,%3}, {%4,%5,%6,%7}, {%8,%9}, {%0,%1,%2,%3};"                \
        : "+f"(d0), "+f"(d1), "+f"(d2), "+f"(d3)                               \
        : "r"(a0), "r"(a1), "r"(a2), "r"(a3), "r"(b0), "r"(b1))

// ---------------------------------------------------------------------------
// C[M,N] = A[M,K] @ B[N,K]^T  via tf32 mma.sync.m16n8k8, fp32 accumulate.
// Block tile 128x128, K-step 16, 256 threads, double-buffered smem.
// ---------------------------------------------------------------------------
#define GS 2560                       // one 128x16 buffer (stride 20) in u32
#define GEMM_SMEM (4 * GS * 4)        // 80 KB

__global__ __launch_bounds__(256) void tgemm_nt(const float* __restrict__ A,
                                                const float* __restrict__ B,
                                                float* __restrict__ C,
                                                int N, int K) {
    extern __shared__ uint32_t dynsm[];
    uint32_t* As = dynsm;             // [2][128*20]
    uint32_t* Bs = dynsm + 2 * GS;    // [2][128*20]
    const int tid = threadIdx.x;
    const int bm = blockIdx.y * 128;
    const int bn = blockIdx.x * 128;
    const int wid = tid >> 5, lane = tid & 31;
    const int g = lane >> 2, t = lane & 3;
    const int wm = (wid & 1) * 64;
    const int wn = (wid >> 1) * 32;

    const int r0 = tid >> 2;
    const int c4 = (tid & 3) << 2;
    const float* ApL = A + (size_t)(bm + r0) * K + c4;
    const float* ApH = A + (size_t)(bm + r0 + 64) * K + c4;
    const float* BpL = B + (size_t)(bn + r0) * K + c4;
    const float* BpH = B + (size_t)(bn + r0 + 64) * K + c4;

    float acc[4][4][4];
#pragma unroll
    for (int mi = 0; mi < 4; mi++)
#pragma unroll
        for (int nj = 0; nj < 4; nj++)
#pragma unroll
            for (int r = 0; r < 4; r++) acc[mi][nj][r] = 0.f;

    float4 pa0, pa1, pb0, pb1;
    pa0 = *(const float4*)(ApL);  pa1 = *(const float4*)(ApH);
    pb0 = *(const float4*)(BpL);  pb1 = *(const float4*)(BpH);
    {
        uint32_t ua0[4] = {f2tf32(pa0.x), f2tf32(pa0.y), f2tf32(pa0.z), f2tf32(pa0.w)};
        uint32_t ua1[4] = {f2tf32(pa1.x), f2tf32(pa1.y), f2tf32(pa1.z), f2tf32(pa1.w)};
        uint32_t ub0[4] = {f2tf32(pb0.x), f2tf32(pb0.y), f2tf32(pb0.z), f2tf32(pb0.w)};
        uint32_t ub1[4] = {f2tf32(pb1.x), f2tf32(pb1.y), f2tf32(pb1.z), f2tf32(pb1.w)};
        *(uint4*)&As[r0 * 20 + c4] = *(uint4*)ua0;
        *(uint4*)&As[(r0 + 64) * 20 + c4] = *(uint4*)ua1;
        *(uint4*)&Bs[r0 * 20 + c4] = *(uint4*)ub0;
        *(uint4*)&Bs[(r0 + 64) * 20 + c4] = *(uint4*)ub1;
    }
    __syncthreads();

    int buf = 0;
    for (int k0 = 0; k0 < K; k0 += 16) {
        const int nk = k0 + 16;
        const bool more = (nk < K);
        if (more) {
            pa0 = *(const float4*)(ApL + nk);  pa1 = *(const float4*)(ApH + nk);
            pb0 = *(const float4*)(BpL + nk);  pb1 = *(const float4*)(BpH + nk);
        }

        const uint32_t* Ab = As + buf * GS;
        const uint32_t* Bb = Bs + buf * GS;
#pragma unroll
        for (int kk = 0; kk < 16; kk += 8) {
            uint32_t af[4][4], bf[4][2];
#pragma unroll
            for (int mi = 0; mi < 4; mi++) {
                int m0 = wm + mi * 16;
                af[mi][0] = Ab[(m0 + g) * 20 + kk + t];
                af[mi][1] = Ab[(m0 + g + 8) * 20 + kk + t];
                af[mi][2] = Ab[(m0 + g) * 20 + kk + t + 4];
                af[mi][3] = Ab[(m0 + g + 8) * 20 + kk + t + 4];
            }
#pragma unroll
            for (int nj = 0; nj < 4; nj++) {
                int n0 = wn + nj * 8;
                bf[nj][0] = Bb[(n0 + g) * 20 + kk + t];
                bf[nj][1] = Bb[(n0 + g) * 20 + kk + t + 4];
            }
#pragma unroll
            for (int mi = 0; mi < 4; mi++)
#pragma unroll
                for (int nj = 0; nj < 4; nj++)
                    MMA_TF32(acc[mi][nj][0], acc[mi][nj][1], acc[mi][nj][2], acc[mi][nj][3],
                             af[mi][0], af[mi][1], af[mi][2], af[mi][3],
                             bf[nj][0], bf[nj][1]);
        }

        if (more) {
            uint32_t* An = As + (buf ^ 1) * GS;
            uint32_t* Bn = Bs + (buf ^ 1) * GS;
            uint32_t ua0[4] = {f2tf32(pa0.x), f2tf32(pa0.y), f2tf32(pa0.z), f2tf32(pa0.w)};
            uint32_t ua1[4] = {f2tf32(pa1.x), f2tf32(pa1.y), f2tf32(pa1.z), f2tf32(pa1.w)};
            uint32_t ub0[4] = {f2tf32(pb0.x), f2tf32(pb0.y), f2tf32(pb0.z), f2tf32(pb0.w)};
            uint32_t ub1[4] = {f2tf32(pb1.x), f2tf32(pb1.y), f2tf32(pb1.z), f2tf32(pb1.w)};
            *(uint4*)&An[r0 * 20 + c4] = *(uint4*)ua0;
            *(uint4*)&An[(r0 + 64) * 20 + c4] = *(uint4*)ua1;
            *(uint4*)&Bn[r0 * 20 + c4] = *(uint4*)ub0;
            *(uint4*)&Bn[(r0 + 64) * 20 + c4] = *(uint4*)ub1;
            __syncthreads();
            buf ^= 1;
        }
    }

#pragma unroll
    for (int mi = 0; mi < 4; mi++) {
        int m0 = bm + wm + mi * 16;
#pragma unroll
        for (int nj = 0; nj < 4; nj++) {
            int n0 = bn + wn + nj * 8 + 2 * t;
            *(float2*)(C + (size_t)(m0 + g) * N + n0) =
                make_float2(acc[mi][nj][0], acc[mi][nj][1]);
            *(float2*)(C + (size_t)(m0 + g + 8) * N + n0) =
                make_float2(acc[mi][nj][2], acc[mi][nj][3]);
        }
    }
}

// ---------------------------------------------------------------------------
// RoPE on q and current-k + scatter into head-major buffers; copy v.
// ---------------------------------------------------------------------------
__global__ __launch_bounds__(256) void rope_scatter(const float* __restrict__ cosb,
                                                    const float* __restrict__ sinb) {
    int idx = blockIdx.x * blockDim.x + threadIdx.x;
    if (idx >= B_ * T_ * NH * 64) return;
    int i = idx & 63;
    int h = (idx >> 6) & 15;
    int t = (idx >> 10) & 1023;
    int b = idx >> 20;
    const float* base = g_qkv + (size_t)(b * T_ + t) * (3 * DM);
    float c = cosb[t * 64 + i], s = sinb[t * 64 + i];

    float q1 = base[h * HD + 2 * i], q2 = base[h * HD + 2 * i + 1];
    size_t qo = ((size_t)(b * NH + h) * T_ + t) * HD + 2 * i;
    g_q[qo]     = q1 * c - q2 * s;
    g_q[qo + 1] = q1 * s + q2 * c;

    float k1 = base[DM + h * HD + 2 * i], k2 = base[DM + h * HD + 2 * i + 1];
    size_t ko = ((size_t)(b * NH + h) * KV_ + XL_ + t) * HD + 2 * i;
    g_k[ko]     = k1 * c - k2 * s;
    g_k[ko + 1] = k1 * s + k2 * c;

    g_v[ko]     = base[2 * DM + h * HD + 2 * i];
    g_v[ko + 1] = base[2 * DM + h * HD + 2 * i + 1];
}

// ---------------------------------------------------------------------------
// XL memory: k_xl + pos_emb -> g_k[:,:,0:1024,:] ; v_xl -> g_v[:,:,0:1024,:]
// ---------------------------------------------------------------------------
__global__ __launch_bounds__(256) void xl_prep(const float* __restrict__ k_xl,
                                               const float* __restrict__ v_xl,
                                               const float* __restrict__ pos_emb) {
    int idx = blockIdx.x * blockDim.x + threadIdx.x;
    if (idx >= B_ * XL_ * (DM / 4)) return;
    int c4 = (idx & 511) << 2;
    int n = (idx >> 9) & 1023;
    int b = idx >> 19;
    int h = c4 >> 7;
    int d = c4 & 127;
    float4 kv = *(const float4*)(k_xl + (size_t)(b * XL_ + n) * DM + c4);
    float4 pe = *(const float4*)(pos_emb + (size_t)n * DM + c4);
    float4 vv = *(const float4*)(v_xl + (size_t)(b * XL_ + n) * DM + c4);
    size_t off = ((size_t)(b * NH + h) * KV_ + n) * HD + d;
    *(float4*)(g_k + off) = make_float4(kv.x + pe.x, kv.y + pe.y, kv.z + pe.z, kv.w + pe.w);
    *(float4*)(g_v + off) = vv;
}

// ---------------------------------------------------------------------------
// Flash attention, fully tensorized. grid (T/64, B*NH), 256 threads = 8 warps.
// Phase 1: S = Q K^T  (tf32 mma; warp (wm,wn) covers 16x32 of 64x64 S)
// Phase 2a: cooperative softmax (4 threads/row x 16 cols, smem reductions)
// Phase 2b: O^T = V^T @ P^T (tf32 mma; warp wd covers 16 d-rows x 64 q-cols)
// ---------------------------------------------------------------------------
#define SST 68
#define ATTN_SMEM ((3 * 64 * 132 + 64 * SST + 2 * 256 + 3 * 64) * 4)

__global__ __launch_bounds__(256) void attn_kernel(const int* __restrict__ causal_p) {
    extern __shared__ float sm[];
    uint32_t* Qu = (uint32_t*)sm;              // 64 x 132 tf32
    uint32_t* Ku = Qu + 64 * 132;              // 64 x 132 tf32
    uint32_t* Vu = Ku + 64 * 132;              // 64 x 132 tf32
    float* Ss   = sm + 3 * 64 * 132;           // 64 x 68  (S then P)
    float* pmax = Ss + 64 * SST;               // [4][64]
    float* psum = pmax + 256;                  // [4][64]
    float* m_s  = psum + 256;                  // [64]
    float* l_s  = m_s + 64;                    // [64]
    float* corr_s = l_s + 64;                  // [64]

    const int bh = blockIdx.y;
    const int qt = blockIdx.x;
    const int tid = threadIdx.x;
    const bool causal = (*causal_p) != 0;
    const float scale = 0.08838834764831845f;   // 1/sqrt(128)

    const float* Qg = g_q + ((size_t)bh * T_ + qt * 64) * HD;
    for (int i = tid; i < 64 * 32; i += 256) {
        int r = i >> 5, c4 = (i & 31) << 2;
        float4 q4 = *(const float4*)(Qg + r * HD + c4);
        uint32_t uq[4] = {f2tf32(q4.x), f2tf32(q4.y), f2tf32(q4.z), f2tf32(q4.w)};
        *(uint4*)&Qu[r * 132 + c4] = *(uint4*)uq;
    }
    if (tid < 64) { m_s[tid] = -CUDART_INF_F; l_s[tid] = 0.f; }

    const int wid = tid >> 5, lane = tid & 31;
    const int g = lane >> 2, t = lane & 3;
    const int wm = (wid >> 1) << 4;   // phase-1 warp q offset
    const int wn = (wid & 1) << 5;    // phase-1 warp kv offset
    const int wd = wid << 4;          // phase-2b warp d offset (8 x 16 = 128)
    const int r = tid & 63;           // softmax row
    const int p = tid >> 6;           // softmax column part (16 cols)

    float oacc[8][4];                 // O^T fragments: d rows wd+g/+8, q cols nj*8+2t/+1
#pragma unroll
    for (int nj = 0; nj < 8; nj++)
#pragma unroll
        for (int rr = 0; rr < 4; rr++) oacc[nj][rr] = 0.f;

    for (int k0 = 0; k0 < KV_; k0 += 64) {
        __syncthreads();   // prev PV done before overwriting K/V
        const float* Kg = g_k + ((size_t)bh * KV_ + k0) * HD;
        const float* Vg = g_v + ((size_t)bh * KV_ + k0) * HD;
        for (int i = tid; i < 64 * 32; i += 256) {
            int rr = i >> 5, c4 = (i & 31) << 2;
            float4 k4 = *(const float4*)(Kg + rr * HD + c4);
            float4 v4 = *(const float4*)(Vg + rr * HD + c4);
            uint32_t uk[4] = {f2tf32(k4.x), f2tf32(k4.y), f2tf32(k4.z), f2tf32(k4.w)};
            uint32_t uv[4] = {f2tf32(v4.x), f2tf32(v4.y), f2tf32(v4.z), f2tf32(v4.w)};
            *(uint4*)&Ku[rr * 132 + c4] = *(uint4*)uk;
            *(uint4*)&Vu[rr * 132 + c4] = *(uint4*)uv;
        }
        __syncthreads();

        // ---- phase 1: S = Q K^T ----
        {
            float sacc[4][4];
#pragma unroll
            for (int nj = 0; nj < 4; nj++)
#pragma unroll
                for (int rr = 0; rr < 4; rr++) sacc[nj][rr] = 0.f;
#pragma unroll 4
            for (int kk = 0; kk < HD; kk += 8) {
                uint32_t a0 = Qu[(wm + g) * 132 + kk + t];
                uint32_t a1 = Qu[(wm + g + 8) * 132 + kk + t];
                uint32_t a2 = Qu[(wm + g) * 132 + kk + t + 4];
                uint32_t a3 = Qu[(wm + g + 8) * 132 + kk + t + 4];
#pragma unroll
                for (int nj = 0; nj < 4; nj++) {
                    int n0 = wn + nj * 8;
                    uint32_t b0 = Ku[(n0 + g) * 132 + kk + t];
                    uint32_t b1 = Ku[(n0 + g) * 132 + kk + t + 4];
                    MMA_TF32(sacc[nj][0], sacc[nj][1], sacc[nj][2], sacc[nj][3],
                             a0, a1, a2, a3, b0, b1);
                }
            }
#pragma unroll
            for (int nj = 0; nj < 4; nj++) {
                int col = wn + nj * 8 + 2 * t;
                int colg = k0 + col;
#pragma unroll
                for (int half = 0; half < 2; half++) {
                    int row = wm + g + half * 8;
                    int rowg = qt * 64 + row;
                    float s0 = sacc[nj][half * 2 + 0] * scale;
                    float s1 = sacc[nj][half * 2 + 1] * scale;
                    if (causal) {
                        if (colg > rowg + (KV_ - T_)) s0 = -CUDART_INF_F;
                        if (colg + 1 > rowg + (KV_ - T_)) s1 = -CUDART_INF_F;
                    }
                    Ss[row * SST + col] = s0;
                    Ss[row * SST + col + 1] = s1;
                }
            }
        }
        __syncthreads();

        // ---- phase 2a: cooperative online softmax ----
        float mold = m_s[r];
        {
            float lmax = -CUDART_INF_F;
            const float* srow = Ss + r * SST + p * 16;
#pragma unroll
            for (int j = 0; j < 16; j++) lmax = fmaxf(lmax, srow[j]);
            pmax[p * 64 + r] = lmax;
        }
        __syncthreads();
        {
            float mnew = fmaxf(fmaxf(pmax[r], pmax[64 + r]),
                               fmaxf(pmax[128 + r], pmax[192 + r]));
            mnew = fmaxf(mnew, mold);
            float corr = (mold == -CUDART_INF_F) ? 0.f : __expf(mold - mnew);
            if (p == 0) { m_s[r] = mnew; corr_s[r] = corr; }
            float ps = 0.f;
            float* swrow = Ss + r * SST + p * 16;
#pragma unroll
            for (int j = 0; j < 16; j++) {
                float e = __expf(swrow[j] - mnew);
                swrow[j] = e;
                ps += e;
            }
            psum[p * 64 + r] = ps;
        }
        __syncthreads();
        if (p == 0)
            l_s[r] = l_s[r] * corr_s[r] +
                     psum[r] + psum[64 + r] + psum[128 + r] + psum[192 + r];

        // ---- phase 2b: O^T += V^T @ P^T ----
#pragma unroll
        for (int nj = 0; nj < 8; nj++) {
            float c0 = corr_s[nj * 8 + 2 * t];
            float c1 = corr_s[nj * 8 + 2 * t + 1];
            oacc[nj][0] *= c0; oacc[nj][1] *= c1;
            oacc[nj][2] *= c0; oacc[nj][3] *= c1;
        }
#pragma unroll 2
        for (int kk = 0; kk < 64; kk += 8) {
            uint32_t a0 = Vu[(kk + t) * 132 + wd + g];
            uint32_t a1 = Vu[(kk + t) * 132 + wd + g + 8];
            uint32_t a2 = Vu[(kk + t + 4) * 132 + wd + g];
            uint32_t a3 = Vu[(kk + t + 4) * 132 + wd + g + 8];
#pragma unroll
            for (int nj = 0; nj < 8; nj++) {
                uint32_t b0 = f2tf32(Ss[(nj * 8 + g) * SST + kk + t]);
                uint32_t b1 = f2tf32(Ss[(nj * 8 + g) * SST + kk + t + 4]);
                MMA_TF32(oacc[nj][0], oacc[nj][1], oacc[nj][2], oacc[nj][3],
                         a0, a1, a2, a3, b0, b1);
            }
        }
    }
    __syncthreads();   // l_s final

    // epilogue: y[b, q, h*128 + d] = O^T[d][q] / l[q]
    const int b = bh >> 4, h = bh & 15;
#pragma unroll
    for (int nj = 0; nj < 8; nj++) {
        int q0 = nj * 8 + 2 * t;
        float inv0 = 1.0f / l_s[q0];
        float inv1 = 1.0f / l_s[q0 + 1];
        float* y0 = g_y + (size_t)(b * T_ + qt * 64 + q0) * DM + h * HD;
        float* y1 = y0 + DM;
        y0[wd + g]     = oacc[nj][0] * inv0;
        y1[wd + g]     = oacc[nj][1] * inv1;
        y0[wd + g + 8] = oacc[nj][2] * inv0;
        y1[wd + g + 8] = oacc[nj][3] * inv1;
    }
}

// ---------------------------------------------------------------------------
extern "C" void kernel_launch(void* const* d_in, const int* in_sizes, int n_in,
                              void* d_out, int out_size) {
    const float* x       = (const float*)d_in[0];
    const float* cosb    = (const float*)d_in[1];
    const float* sinb    = (const float*)d_in[2];
    const float* k_xl    = (const float*)d_in[3];
    const float* v_xl    = (const float*)d_in[4];
    const float* pos_emb = (const float*)d_in[5];
    const float* w_qkv   = (const float*)d_in[6];
    const float* w_proj  = (const float*)d_in[7];
    const int*   is_causal = (const int*)d_in[8];
    float* out = (float*)d_out;

    float *qkv_p, *y_p;
    cudaGetSymbolAddress((void**)&qkv_p, g_qkv);
    cudaGetSymbolAddress((void**)&y_p, g_y);

    cudaFuncSetAttribute(tgemm_nt, cudaFuncAttributeMaxDynamicSharedMemorySize, GEMM_SMEM);
    cudaFuncSetAttribute(attn_kernel, cudaFuncAttributeMaxDynamicSharedMemorySize, ATTN_SMEM);

    // 1) qkv = x @ w_qkv^T   (2048 x 6144 x 2048)
    tgemm_nt<<<dim3(3 * DM / 128, BT_ / 128), 256, GEMM_SMEM>>>(x, w_qkv, qkv_p, 3 * DM, DM);

    // 2) RoPE + scatter, XL prep
    rope_scatter<<<(B_ * T_ * NH * 64) / 256, 256>>>(cosb, sinb);
    xl_prep<<<(B_ * XL_ * (DM / 4)) / 256, 256>>>(k_xl, v_xl, pos_emb);

    // 3) attention (tf32 mma for S and PV)
    attn_kernel<<<dim3(T_ / 64, B_ * NH), 256, ATTN_SMEM>>>(is_causal);

    // 4) out = y @ w_proj^T  (2048 x 2048 x 2048)
    tgemm_nt<<<dim3(DM / 128, BT_ / 128), 256, GEMM_SMEM>>>(y_p, w_proj, out, DM, DM);
}